// round 9
// baseline (speedup 1.0000x reference)
#include <cuda_runtime.h>
#include <cuda_bf16.h>
#include <mma.h>
#include <math.h>
#include <stdint.h>

using namespace nvcuda;

#define NROWS 8192
#define DDIM  512
#define NQKV  1536
#define NG    64
#define MAXG  512

// ---------------------------------------------------------------------------
// Scratch (device globals: allocation-free rule)
// ---------------------------------------------------------------------------
__device__ float g_qkv[(size_t)NROWS * NQKV];        // fused q|k|v fp32
__device__ float g_S[(size_t)NG * MAXG * MAXG];      // scores, then packed P
__device__ __nv_bfloat16 g_xh[NROWS * DDIM];         // A operand hi (x, then att)
__device__ __nv_bfloat16 g_xl[NROWS * DDIM];         // A operand lo
__device__ __nv_bfloat16 g_pwh[DDIM * NQKV];         // packed Wq|Wk|Wv hi
__device__ __nv_bfloat16 g_pwl[DDIM * NQKV];
__device__ __nv_bfloat16 g_owh[DDIM * DDIM];         // Wo hi
__device__ __nv_bfloat16 g_owl[DDIM * DDIM];
__device__ float g_btq[16 * NQKV];                   // broadcast bias tiles
__device__ float g_bto[16 * DDIM];
__device__ int   g_cnt[NG];
__device__ int   g_mem[NG * MAXG];

__device__ __forceinline__ void bsplit(float v, __nv_bfloat16& h, __nv_bfloat16& l) {
    h = __float2bfloat16(v);
    l = __float2bfloat16(v - __bfloat162float(h));
}

// ---------------------------------------------------------------------------
// Small kernels
// ---------------------------------------------------------------------------
__global__ void zero_cnt_kernel() {
    if (threadIdx.x < NG) g_cnt[threadIdx.x] = 0;
}

__global__ void build_groups_kernel(const int* __restrict__ labels) {
    int i = blockIdx.x * blockDim.x + threadIdx.x;
    if (i < NROWS) {
        int lb = labels[i];
        if (lb >= 0) {
            int pos = atomicAdd(&g_cnt[lb], 1);
            if (pos < MAXG) g_mem[lb * MAXG + pos] = i;
        }
    }
}

// fp32 -> (bf16 hi, bf16 lo) elementwise split, float4 vectorized
__global__ void split_kernel(const float* __restrict__ src,
                             __nv_bfloat16* __restrict__ hi,
                             __nv_bfloat16* __restrict__ lo) {
    int i = blockIdx.x * blockDim.x + threadIdx.x;      // float4 index
    float4 f = ((const float4*)src)[i];
    __nv_bfloat16 h0, h1, h2, h3, l0, l1, l2, l3;
    bsplit(f.x, h0, l0); bsplit(f.y, h1, l1);
    bsplit(f.z, h2, l2); bsplit(f.w, h3, l3);
    __nv_bfloat162* ph = (__nv_bfloat162*)hi;
    __nv_bfloat162* pl = (__nv_bfloat162*)lo;
    ph[i * 2 + 0] = __nv_bfloat162(h0, h1);
    ph[i * 2 + 1] = __nv_bfloat162(h2, h3);
    pl[i * 2 + 0] = __nv_bfloat162(l0, l1);
    pl[i * 2 + 1] = __nv_bfloat162(l2, l3);
}

// Pack Wq|Wk|Wv into [512][1536] split layout; Wo into [512][512] split
__global__ void pack_weights_kernel(const float* __restrict__ Wq,
                                    const float* __restrict__ Wk,
                                    const float* __restrict__ Wv,
                                    const float* __restrict__ Wo) {
    int i = blockIdx.x * blockDim.x + threadIdx.x;   // 0 .. 4*512*512-1
    int w = i >> 18;
    int r = i & 262143;
    const float* W = (w == 0) ? Wq : (w == 1) ? Wk : (w == 2) ? Wv : Wo;
    float v = W[r];
    __nv_bfloat16 h, l;
    bsplit(v, h, l);
    if (w < 3) {
        int k = r >> 9, n = r & 511;
        size_t o = (size_t)k * NQKV + w * 512 + n;
        g_pwh[o] = h; g_pwl[o] = l;
    } else {
        g_owh[r] = h; g_owl[r] = l;
    }
}

// Broadcast bias tiles: [16][1536] for qkv, [16][512] for o
__global__ void bias_tile_kernel(const float* __restrict__ bq,
                                 const float* __restrict__ bk,
                                 const float* __restrict__ bv,
                                 const float* __restrict__ bo) {
    int i = blockIdx.x * blockDim.x + threadIdx.x;   // 0 .. 16*2048-1
    int row = i >> 11;
    int col = i & 2047;
    if (col < NQKV) {
        int w = col >> 9, c = col & 511;
        g_btq[row * NQKV + col] = (w == 0) ? bq[c] : (w == 1) ? bk[c] : bv[c];
    } else {
        int c = col - NQKV;
        g_bto[row * DDIM + c] = bo[c];
    }
}

// Zero att-split rows for invalid labels (valid rows get overwritten by PV)
__global__ void zero_invalid_kernel(const int* __restrict__ labels) {
    int i = blockIdx.x * blockDim.x + threadIdx.x;   // 0 .. 8192*64-1 (uint4)
    int row = i >> 6, c = i & 63;
    if (labels[row] < 0) {
        uint4 z = make_uint4(0, 0, 0, 0);
        ((uint4*)g_xh)[(size_t)row * 64 + c] = z;
        ((uint4*)g_xl)[(size_t)row * 64 + c] = z;
    }
}

// ---------------------------------------------------------------------------
// WMMA bf16-split GEMM: C[8192,N] = A[8192,512] @ B[512,N] + bias (fp32-acc)
// grid = (N/128, 64), block = 256 (8 warps 2x4), warp tile 64x32.
// ---------------------------------------------------------------------------
#define KC    32
#define LDA   48     // KC + 16 pad
#define LDB   144    // 128 + 16 pad

__global__ __launch_bounds__(256)
void wmma_gemm_kernel(const __nv_bfloat16* __restrict__ Ah,
                      const __nv_bfloat16* __restrict__ Al,
                      const __nv_bfloat16* __restrict__ Bh,
                      const __nv_bfloat16* __restrict__ Bl,
                      int ldb,
                      const float* __restrict__ btile,  // [16][ldc]
                      float* __restrict__ C, int ldc) {
    __shared__ __nv_bfloat16 sAh[128][LDA];
    __shared__ __nv_bfloat16 sAl[128][LDA];
    __shared__ __nv_bfloat16 sBh[KC][LDB];
    __shared__ __nv_bfloat16 sBl[KC][LDB];

    const int tid = threadIdx.x;
    const int wid = tid >> 5;
    const int wRow = (wid & 1) * 64;
    const int wCol = (wid >> 1) * 32;
    const int rowBase = blockIdx.y * 128;
    const int colBase = blockIdx.x * 128;

    wmma::fragment<wmma::accumulator, 16, 16, 16, float> acc[4][2];
#pragma unroll
    for (int mi = 0; mi < 4; mi++)
#pragma unroll
        for (int ni = 0; ni < 2; ni++)
            wmma::load_matrix_sync(acc[mi][ni],
                                   btile + (colBase + wCol + ni * 16),
                                   ldc, wmma::mem_row_major);

    for (int kc = 0; kc < DDIM; kc += KC) {
#pragma unroll
        for (int s = 0; s < 2; s++) {
            int idx = tid * 2 + s;            // 0..511
            int r = idx >> 2;
            int c = (idx & 3) * 8;
            size_t ga = (size_t)(rowBase + r) * DDIM + kc + c;
            *(uint4*)&sAh[r][c] = *(const uint4*)(Ah + ga);
            *(uint4*)&sAl[r][c] = *(const uint4*)(Al + ga);
        }
#pragma unroll
        for (int s = 0; s < 2; s++) {
            int idx = tid * 2 + s;
            int r = idx >> 4;
            int c = (idx & 15) * 8;
            size_t gb = (size_t)(kc + r) * ldb + colBase + c;
            *(uint4*)&sBh[r][c] = *(const uint4*)(Bh + gb);
            *(uint4*)&sBl[r][c] = *(const uint4*)(Bl + gb);
        }
        __syncthreads();

#pragma unroll
        for (int k16 = 0; k16 < KC; k16 += 16) {
            wmma::fragment<wmma::matrix_a, 16, 16, 16, __nv_bfloat16, wmma::row_major> ah[4], al[4];
            wmma::fragment<wmma::matrix_b, 16, 16, 16, __nv_bfloat16, wmma::row_major> bh[2], bl[2];
#pragma unroll
            for (int mi = 0; mi < 4; mi++) {
                wmma::load_matrix_sync(ah[mi], &sAh[wRow + mi * 16][k16], LDA);
                wmma::load_matrix_sync(al[mi], &sAl[wRow + mi * 16][k16], LDA);
            }
#pragma unroll
            for (int ni = 0; ni < 2; ni++) {
                wmma::load_matrix_sync(bh[ni], &sBh[k16][wCol + ni * 16], LDB);
                wmma::load_matrix_sync(bl[ni], &sBl[k16][wCol + ni * 16], LDB);
            }
#pragma unroll
            for (int mi = 0; mi < 4; mi++)
#pragma unroll
                for (int ni = 0; ni < 2; ni++) {
                    wmma::mma_sync(acc[mi][ni], ah[mi], bh[ni], acc[mi][ni]);
                    wmma::mma_sync(acc[mi][ni], ah[mi], bl[ni], acc[mi][ni]);
                    wmma::mma_sync(acc[mi][ni], al[mi], bh[ni], acc[mi][ni]);
                }
        }
        __syncthreads();
    }

#pragma unroll
    for (int mi = 0; mi < 4; mi++)
#pragma unroll
        for (int ni = 0; ni < 2; ni++)
            wmma::store_matrix_sync(
                &C[(size_t)(rowBase + wRow + mi * 16) * ldc + colBase + wCol + ni * 16],
                acc[mi][ni], ldc, wmma::mem_row_major);
}

// ---------------------------------------------------------------------------
// Phase 1: scores. S[g][i][j] = Q_g[i] . K_g[j]  (unscaled), 128x128 tiles.
// grid (NG, 4, 4), block 256. Gathered rows, on-the-fly bf16 split, 3-combo.
// ---------------------------------------------------------------------------
#define SLDA 72     // 64 + 8 pad

__global__ __launch_bounds__(256)
void scores_kernel() {
    const int g = blockIdx.x, qt = blockIdx.y, kt = blockIdx.z;
    const int m = g_cnt[g];
    if (qt * 128 >= m || kt * 128 >= m) return;
    const int* mem = &g_mem[g * MAXG];

    extern __shared__ __nv_bfloat16 sm[];
    __nv_bfloat16* sQh = sm;
    __nv_bfloat16* sQl = sm + 128 * SLDA;
    __nv_bfloat16* sKh = sm + 2 * 128 * SLDA;
    __nv_bfloat16* sKl = sm + 3 * 128 * SLDA;

    const int tid = threadIdx.x;
    const int wid = tid >> 5;
    const int wRow = (wid & 1) * 64;
    const int wCol = (wid >> 1) * 32;

    wmma::fragment<wmma::accumulator, 16, 16, 16, float> acc[4][2];
#pragma unroll
    for (int mi = 0; mi < 4; mi++)
#pragma unroll
        for (int ni = 0; ni < 2; ni++)
            wmma::fill_fragment(acc[mi][ni], 0.f);

    for (int kc = 0; kc < DDIM; kc += 64) {
        // Q tile 128x64 gathered
        for (int t = tid; t < 2048; t += 256) {
            int r = t >> 4, c4 = (t & 15) << 2;
            int qi = qt * 128 + r;
            float4 f = make_float4(0.f, 0.f, 0.f, 0.f);
            if (qi < m)
                f = *(const float4*)&g_qkv[(size_t)mem[qi] * NQKV + kc + c4];
            __nv_bfloat16 h0, h1, h2, h3, l0, l1, l2, l3;
            bsplit(f.x, h0, l0); bsplit(f.y, h1, l1);
            bsplit(f.z, h2, l2); bsplit(f.w, h3, l3);
            __nv_bfloat162* ph = (__nv_bfloat162*)&sQh[r * SLDA + c4];
            __nv_bfloat162* pl = (__nv_bfloat162*)&sQl[r * SLDA + c4];
            ph[0] = __nv_bfloat162(h0, h1); ph[1] = __nv_bfloat162(h2, h3);
            pl[0] = __nv_bfloat162(l0, l1); pl[1] = __nv_bfloat162(l2, l3);
        }
        // K tile 128x64 gathered (offset +512 in qkv)
        for (int t = tid; t < 2048; t += 256) {
            int r = t >> 4, c4 = (t & 15) << 2;
            int ki = kt * 128 + r;
            float4 f = make_float4(0.f, 0.f, 0.f, 0.f);
            if (ki < m)
                f = *(const float4*)&g_qkv[(size_t)mem[ki] * NQKV + 512 + kc + c4];
            __nv_bfloat16 h0, h1, h2, h3, l0, l1, l2, l3;
            bsplit(f.x, h0, l0); bsplit(f.y, h1, l1);
            bsplit(f.z, h2, l2); bsplit(f.w, h3, l3);
            __nv_bfloat162* ph = (__nv_bfloat162*)&sKh[r * SLDA + c4];
            __nv_bfloat162* pl = (__nv_bfloat162*)&sKl[r * SLDA + c4];
            ph[0] = __nv_bfloat162(h0, h1); ph[1] = __nv_bfloat162(h2, h3);
            pl[0] = __nv_bfloat162(l0, l1); pl[1] = __nv_bfloat162(l2, l3);
        }
        __syncthreads();

#pragma unroll
        for (int k16 = 0; k16 < 64; k16 += 16) {
            wmma::fragment<wmma::matrix_a, 16, 16, 16, __nv_bfloat16, wmma::row_major> ah[4], al[4];
            wmma::fragment<wmma::matrix_b, 16, 16, 16, __nv_bfloat16, wmma::col_major> bh[2], bl[2];
#pragma unroll
            for (int mi = 0; mi < 4; mi++) {
                wmma::load_matrix_sync(ah[mi], &sQh[(wRow + mi * 16) * SLDA + k16], SLDA);
                wmma::load_matrix_sync(al[mi], &sQl[(wRow + mi * 16) * SLDA + k16], SLDA);
            }
#pragma unroll
            for (int ni = 0; ni < 2; ni++) {
                wmma::load_matrix_sync(bh[ni], &sKh[(wCol + ni * 16) * SLDA + k16], SLDA);
                wmma::load_matrix_sync(bl[ni], &sKl[(wCol + ni * 16) * SLDA + k16], SLDA);
            }
#pragma unroll
            for (int mi = 0; mi < 4; mi++)
#pragma unroll
                for (int ni = 0; ni < 2; ni++) {
                    wmma::mma_sync(acc[mi][ni], ah[mi], bh[ni], acc[mi][ni]);
                    wmma::mma_sync(acc[mi][ni], ah[mi], bl[ni], acc[mi][ni]);
                    wmma::mma_sync(acc[mi][ni], al[mi], bh[ni], acc[mi][ni]);
                }
        }
        __syncthreads();
    }

#pragma unroll
    for (int mi = 0; mi < 4; mi++)
#pragma unroll
        for (int ni = 0; ni < 2; ni++)
            wmma::store_matrix_sync(
                &g_S[((size_t)g * MAXG + qt * 128 + wRow + mi * 16) * MAXG
                     + kt * 128 + wCol + ni * 16],
                acc[mi][ni], MAXG, wmma::mem_row_major);
}

// ---------------------------------------------------------------------------
// Phase 2: softmax per row; writes P back in place as packed bf16 (hi|lo<<16)
// grid (NG, 64), block 256 (warp per row)
// ---------------------------------------------------------------------------
__global__ __launch_bounds__(256)
void softmax_kernel() {
    const int g = blockIdx.x;
    const int m = g_cnt[g];
    const int wid = threadIdx.x >> 5, lane = threadIdx.x & 31;
    const int i = blockIdx.y * 8 + wid;
    if (i >= m) return;
    float* rowp = &g_S[((size_t)g * MAXG + i) * MAXG];
    const float scale = 0.044194173824159216f;   // 1/sqrt(512)

    float vals[16];
    const int nt = (m + 31) >> 5;
    float mx = -1e30f;
    for (int t = 0; t < nt; t++) {
        int j = lane + t * 32;
        float v = (j < m) ? rowp[j] * scale : -1e30f;
        vals[t] = v;
        mx = fmaxf(mx, v);
    }
#pragma unroll
    for (int o = 16; o; o >>= 1) mx = fmaxf(mx, __shfl_xor_sync(0xffffffffu, mx, o));
    float sum = 0.f;
    for (int t = 0; t < nt; t++) {
        int j = lane + t * 32;
        float e = (j < m) ? __expf(vals[t] - mx) : 0.f;
        vals[t] = e;
        sum += e;
    }
#pragma unroll
    for (int o = 16; o; o >>= 1) sum += __shfl_xor_sync(0xffffffffu, sum, o);
    float inv = 1.f / sum;
    for (int t = 0; t < nt; t++) {
        int j = lane + t * 32;
        if (j < m) {
            float p = vals[t] * inv;
            __nv_bfloat16 h, l;
            bsplit(p, h, l);
            unsigned u = (unsigned)__bfloat16_as_ushort(h)
                       | ((unsigned)__bfloat16_as_ushort(l) << 16);
            ((unsigned*)rowp)[j] = u;
        }
    }
}

// ---------------------------------------------------------------------------
// Phase 3: out = P @ V_g, scattered + bf16-split directly into g_xh/g_xl.
// grid (NG, 4, 4=ntiles), block 256.
// ---------------------------------------------------------------------------
#define PLD 72
#define VLD 136

__global__ __launch_bounds__(256)
void pv_kernel() {
    const int g = blockIdx.x, qt = blockIdx.y, nt = blockIdx.z;
    const int m = g_cnt[g];
    if (qt * 128 >= m) return;
    const int* mem = &g_mem[g * MAXG];
    const int nbase = nt * 128;

    extern __shared__ __nv_bfloat16 sm2[];
    __nv_bfloat16* sPh = sm2;
    __nv_bfloat16* sPl = sm2 + 128 * PLD;
    __nv_bfloat16* sVh = sm2 + 2 * 128 * PLD;
    __nv_bfloat16* sVl = sVh + 64 * VLD;

    const int tid = threadIdx.x;
    const int wid = tid >> 5;
    const int wRow = (wid & 1) * 64;
    const int wCol = (wid >> 1) * 32;

    wmma::fragment<wmma::accumulator, 16, 16, 16, float> acc[4][2];
#pragma unroll
    for (int mi = 0; mi < 4; mi++)
#pragma unroll
        for (int ni = 0; ni < 2; ni++)
            wmma::fill_fragment(acc[mi][ni], 0.f);

    const int JT = (m + 63) >> 6;
    for (int jc = 0; jc < JT; jc++) {
        const int j0 = jc * 64;
        // P tile 128x64 from packed g_S
        for (int t = tid; t < 8192; t += 256) {
            int r = t >> 6, c = t & 63;
            int j = j0 + c;
            unsigned u = 0;
            if (j < m)
                u = *(const unsigned*)&g_S[((size_t)g * MAXG + qt * 128 + r) * MAXG + j];
            sPh[r * PLD + c] = __ushort_as_bfloat16((unsigned short)(u & 0xffffu));
            sPl[r * PLD + c] = __ushort_as_bfloat16((unsigned short)(u >> 16));
        }
        // V tile 64x128 gathered (offset +1024 in qkv), split
        for (int t = tid; t < 2048; t += 256) {
            int r = t >> 5, c4 = (t & 31) << 2;
            int j = j0 + r;
            float4 f = make_float4(0.f, 0.f, 0.f, 0.f);
            if (j < m)
                f = *(const float4*)&g_qkv[(size_t)mem[j] * NQKV + 1024 + nbase + c4];
            __nv_bfloat16 h0, h1, h2, h3, l0, l1, l2, l3;
            bsplit(f.x, h0, l0); bsplit(f.y, h1, l1);
            bsplit(f.z, h2, l2); bsplit(f.w, h3, l3);
            __nv_bfloat162* ph = (__nv_bfloat162*)&sVh[r * VLD + c4];
            __nv_bfloat162* pl = (__nv_bfloat162*)&sVl[r * VLD + c4];
            ph[0] = __nv_bfloat162(h0, h1); ph[1] = __nv_bfloat162(h2, h3);
            pl[0] = __nv_bfloat162(l0, l1); pl[1] = __nv_bfloat162(l2, l3);
        }
        __syncthreads();

#pragma unroll
        for (int k16 = 0; k16 < 64; k16 += 16) {
            wmma::fragment<wmma::matrix_a, 16, 16, 16, __nv_bfloat16, wmma::row_major> ah[4], al[4];
            wmma::fragment<wmma::matrix_b, 16, 16, 16, __nv_bfloat16, wmma::row_major> bh[2], bl[2];
#pragma unroll
            for (int mi = 0; mi < 4; mi++) {
                wmma::load_matrix_sync(ah[mi], &sPh[(wRow + mi * 16) * PLD + k16], PLD);
                wmma::load_matrix_sync(al[mi], &sPl[(wRow + mi * 16) * PLD + k16], PLD);
            }
#pragma unroll
            for (int ni = 0; ni < 2; ni++) {
                wmma::load_matrix_sync(bh[ni], &sVh[k16 * VLD + wCol + ni * 16], VLD);
                wmma::load_matrix_sync(bl[ni], &sVl[k16 * VLD + wCol + ni * 16], VLD);
            }
#pragma unroll
            for (int mi = 0; mi < 4; mi++)
#pragma unroll
                for (int ni = 0; ni < 2; ni++) {
                    wmma::mma_sync(acc[mi][ni], ah[mi], bh[ni], acc[mi][ni]);
                    wmma::mma_sync(acc[mi][ni], ah[mi], bl[ni], acc[mi][ni]);
                    wmma::mma_sync(acc[mi][ni], al[mi], bh[ni], acc[mi][ni]);
                }
        }
        __syncthreads();
    }

    // stage output tile in smem (reuse), then scatter + split to g_xh/g_xl
    float* so = (float*)sm2;   // 128 x 132
#pragma unroll
    for (int mi = 0; mi < 4; mi++)
#pragma unroll
        for (int ni = 0; ni < 2; ni++)
            wmma::store_matrix_sync(&so[(wRow + mi * 16) * 132 + wCol + ni * 16],
                                    acc[mi][ni], 132, wmma::mem_row_major);
    __syncthreads();

    for (int t = tid; t < 4096; t += 256) {
        int r = t >> 5, c4 = (t & 31) << 2;
        int i = qt * 128 + r;
        if (i < m) {
            int row = mem[i];
            float4 f = *(float4*)&so[r * 132 + c4];
            __nv_bfloat16 h0, h1, h2, h3, l0, l1, l2, l3;
            bsplit(f.x, h0, l0); bsplit(f.y, h1, l1);
            bsplit(f.z, h2, l2); bsplit(f.w, h3, l3);
            size_t o = ((size_t)row * DDIM + nbase + c4) >> 1;   // bf162 index
            ((__nv_bfloat162*)g_xh)[o]     = __nv_bfloat162(h0, h1);
            ((__nv_bfloat162*)g_xh)[o + 1] = __nv_bfloat162(h2, h3);
            ((__nv_bfloat162*)g_xl)[o]     = __nv_bfloat162(l0, l1);
            ((__nv_bfloat162*)g_xl)[o + 1] = __nv_bfloat162(l2, l3);
        }
    }
}

// ---------------------------------------------------------------------------
// Launch
// ---------------------------------------------------------------------------
extern "C" void kernel_launch(void* const* d_in, const int* in_sizes, int n_in,
                              void* d_out, int out_size) {
    const float* x      = (const float*)d_in[0];
    const int*   labels = (const int*)  d_in[1];
    const float* Wq     = (const float*)d_in[2];
    const float* bq     = (const float*)d_in[3];
    const float* Wk     = (const float*)d_in[4];
    const float* bk     = (const float*)d_in[5];
    const float* Wv     = (const float*)d_in[6];
    const float* bv     = (const float*)d_in[7];
    const float* Wo     = (const float*)d_in[8];
    const float* bo     = (const float*)d_in[9];
    float* out = (float*)d_out;

    float *qkv, *btq, *bto;
    __nv_bfloat16 *xh, *xl, *pwh, *pwl, *owh, *owl;
    cudaGetSymbolAddress((void**)&qkv, g_qkv);
    cudaGetSymbolAddress((void**)&btq, g_btq);
    cudaGetSymbolAddress((void**)&bto, g_bto);
    cudaGetSymbolAddress((void**)&xh,  g_xh);
    cudaGetSymbolAddress((void**)&xl,  g_xl);
    cudaGetSymbolAddress((void**)&pwh, g_pwh);
    cudaGetSymbolAddress((void**)&pwl, g_pwl);
    cudaGetSymbolAddress((void**)&owh, g_owh);
    cudaGetSymbolAddress((void**)&owl, g_owl);

    const int scores_smem = 4 * 128 * SLDA * (int)sizeof(__nv_bfloat16);    // 73728
    const int pv_smem = (2 * 128 * PLD + 2 * 64 * VLD) * (int)sizeof(__nv_bfloat16); // 71680
    cudaFuncSetAttribute(scores_kernel, cudaFuncAttributeMaxDynamicSharedMemorySize, scores_smem);
    cudaFuncSetAttribute(pv_kernel, cudaFuncAttributeMaxDynamicSharedMemorySize, pv_smem);

    zero_cnt_kernel<<<1, 64>>>();
    build_groups_kernel<<<NROWS / 256, 256>>>(labels);
    split_kernel<<<(NROWS * DDIM / 4) / 256, 256>>>(x, xh, xl);
    pack_weights_kernel<<<(4 * DDIM * DDIM) / 256, 256>>>(Wq, Wk, Wv, Wo);
    bias_tile_kernel<<<(16 * 2048) / 256, 256>>>(bq, bk, bv, bo);

    // fused QKV projection: [8192,512] @ [512,1536] + bias
    wmma_gemm_kernel<<<dim3(NQKV / 128, NROWS / 128), 256>>>(
        xh, xl, pwh, pwl, NQKV, btq, qkv, NQKV);

    scores_kernel<<<dim3(NG, 4, 4), 256, scores_smem>>>();
    softmax_kernel<<<dim3(NG, 64), 256>>>();
    zero_invalid_kernel<<<(NROWS * 64) / 256, 256>>>(labels);
    pv_kernel<<<dim3(NG, 4, 4), 256, pv_smem>>>();

    // output projection straight into d_out
    wmma_gemm_kernel<<<dim3(DDIM / 128, NROWS / 128), 256>>>(
        xh, xl, owh, owl, DDIM, bto, out, DDIM);
}

// round 11
// speedup vs baseline: 1.8418x; 1.8418x over previous
#include <cuda_runtime.h>
#include <cuda_bf16.h>
#include <mma.h>
#include <math.h>
#include <stdint.h>

using namespace nvcuda;

#define NROWS 8192
#define DDIM  512
#define NQKV  1536
#define NG    64
#define MAXG  512

// ---------------------------------------------------------------------------
// Scratch (device globals: allocation-free rule)
// ---------------------------------------------------------------------------
__device__ float g_qkv[(size_t)NROWS * NQKV];        // fused q|k|v fp32
__device__ float g_S[(size_t)NG * MAXG * MAXG];      // scores, then packed P
__device__ __nv_bfloat16 g_xh[NROWS * DDIM];         // A operand hi (x, then att)
__device__ __nv_bfloat16 g_xl[NROWS * DDIM];         // A operand lo
__device__ __nv_bfloat16 g_pwh[DDIM * NQKV];         // packed Wq|Wk|Wv hi
__device__ __nv_bfloat16 g_pwl[DDIM * NQKV];
__device__ __nv_bfloat16 g_owh[DDIM * DDIM];         // Wo hi
__device__ __nv_bfloat16 g_owl[DDIM * DDIM];
__device__ float g_btq[16 * NQKV];                   // broadcast bias tiles
__device__ float g_bto[16 * DDIM];
__device__ int   g_cnt[NG];
__device__ int   g_mem[NG * MAXG];

__device__ __forceinline__ void bsplit(float v, __nv_bfloat16& h, __nv_bfloat16& l) {
    h = __float2bfloat16(v);
    l = __float2bfloat16(v - __bfloat162float(h));
}

__device__ __forceinline__ uint32_t smem_u32(const void* p) {
    uint32_t a;
    asm("{ .reg .u64 t; cvta.to.shared.u64 t, %1; cvt.u32.u64 %0, t; }"
        : "=r"(a) : "l"(p));
    return a;
}

__device__ __forceinline__ void cp16(void* sdst, const void* gsrc) {
    asm volatile("cp.async.cg.shared.global [%0], [%1], 16;"
                 :: "r"(smem_u32(sdst)), "l"(gsrc));
}
#define CP_COMMIT() asm volatile("cp.async.commit_group;" ::: "memory")
template <int N>
__device__ __forceinline__ void cp_wait() {
    asm volatile("cp.async.wait_group %0;" :: "n"(N) : "memory");
}

// ---------------------------------------------------------------------------
// Small kernels
// ---------------------------------------------------------------------------
__global__ void zero_cnt_kernel() {
    if (threadIdx.x < NG) g_cnt[threadIdx.x] = 0;
}

__global__ void build_groups_kernel(const int* __restrict__ labels) {
    int i = blockIdx.x * blockDim.x + threadIdx.x;
    if (i < NROWS) {
        int lb = labels[i];
        if (lb >= 0) {
            int pos = atomicAdd(&g_cnt[lb], 1);
            if (pos < MAXG) g_mem[lb * MAXG + pos] = i;
        }
    }
}

// fp32 -> (bf16 hi, bf16 lo) elementwise split, float4 vectorized
__global__ void split_kernel(const float* __restrict__ src,
                             __nv_bfloat16* __restrict__ hi,
                             __nv_bfloat16* __restrict__ lo) {
    int i = blockIdx.x * blockDim.x + threadIdx.x;      // float4 index
    float4 f = ((const float4*)src)[i];
    __nv_bfloat16 h0, h1, h2, h3, l0, l1, l2, l3;
    bsplit(f.x, h0, l0); bsplit(f.y, h1, l1);
    bsplit(f.z, h2, l2); bsplit(f.w, h3, l3);
    __nv_bfloat162* ph = (__nv_bfloat162*)hi;
    __nv_bfloat162* pl = (__nv_bfloat162*)lo;
    ph[i * 2 + 0] = __nv_bfloat162(h0, h1);
    ph[i * 2 + 1] = __nv_bfloat162(h2, h3);
    pl[i * 2 + 0] = __nv_bfloat162(l0, l1);
    pl[i * 2 + 1] = __nv_bfloat162(l2, l3);
}

// Pack Wq|Wk|Wv into [512][1536] split layout; Wo into [512][512] split
__global__ void pack_weights_kernel(const float* __restrict__ Wq,
                                    const float* __restrict__ Wk,
                                    const float* __restrict__ Wv,
                                    const float* __restrict__ Wo) {
    int i = blockIdx.x * blockDim.x + threadIdx.x;   // 0 .. 4*512*512-1
    int w = i >> 18;
    int r = i & 262143;
    const float* W = (w == 0) ? Wq : (w == 1) ? Wk : (w == 2) ? Wv : Wo;
    float v = W[r];
    __nv_bfloat16 h, l;
    bsplit(v, h, l);
    if (w < 3) {
        int k = r >> 9, n = r & 511;
        size_t o = (size_t)k * NQKV + w * 512 + n;
        g_pwh[o] = h; g_pwl[o] = l;
    } else {
        g_owh[r] = h; g_owl[r] = l;
    }
}

// Broadcast bias tiles: [16][1536] for qkv, [16][512] for o
__global__ void bias_tile_kernel(const float* __restrict__ bq,
                                 const float* __restrict__ bk,
                                 const float* __restrict__ bv,
                                 const float* __restrict__ bo) {
    int i = blockIdx.x * blockDim.x + threadIdx.x;   // 0 .. 16*2048-1
    int row = i >> 11;
    int col = i & 2047;
    if (col < NQKV) {
        int w = col >> 9, c = col & 511;
        g_btq[row * NQKV + col] = (w == 0) ? bq[c] : (w == 1) ? bk[c] : bv[c];
    } else {
        int c = col - NQKV;
        g_bto[row * DDIM + c] = bo[c];
    }
}

// Zero att-split rows for invalid labels (valid rows get overwritten by PV)
__global__ void zero_invalid_kernel(const int* __restrict__ labels) {
    int i = blockIdx.x * blockDim.x + threadIdx.x;   // 0 .. 8192*64-1 (uint4)
    int row = i >> 6, c = i & 63;
    if (labels[row] < 0) {
        uint4 z = make_uint4(0, 0, 0, 0);
        ((uint4*)g_xh)[(size_t)row * 64 + c] = z;
        ((uint4*)g_xl)[(size_t)row * 64 + c] = z;
    }
}

// ---------------------------------------------------------------------------
// WMMA bf16-split GEMM, cp.async double-buffered.
// C[8192,LDC] = A[8192,512] @ B[512,LDB] + bias.  Templated strides.
// grid = (LDC/128, 64), block = 256 (8 warps 2x4), warp tile 64x32.
// ---------------------------------------------------------------------------
#define KC    32
#define LDA_S 48     // KC + 16 pad (bf16 elems)
#define LDB_S 144    // 128 + 16 pad

// smem stage layout (bytes)
#define OFF_AH 0
#define OFF_AL (128 * LDA_S * 2)                      // 12288
#define OFF_BH (2 * 128 * LDA_S * 2)                  // 24576
#define OFF_BL (2 * 128 * LDA_S * 2 + KC * LDB_S * 2) // 33792
#define STAGE_BYTES (2 * 128 * LDA_S * 2 + 2 * KC * LDB_S * 2)  // 43008
#define GEMM_SMEM (2 * STAGE_BYTES)                   // 86016

template <int LDBG, int LDC>
__global__ __launch_bounds__(256, 2)
void wmma_gemm_kernel(const __nv_bfloat16* __restrict__ Ah,
                      const __nv_bfloat16* __restrict__ Al,
                      const __nv_bfloat16* __restrict__ Bh,
                      const __nv_bfloat16* __restrict__ Bl,
                      const float* __restrict__ btile,  // [16][LDC]
                      float* __restrict__ C) {
    extern __shared__ char smem[];

    const int tid = threadIdx.x;
    const int wid = tid >> 5;
    const int wRow = (wid & 1) * 64;
    const int wCol = (wid >> 1) * 32;
    const int rowBase = blockIdx.y * 128;
    const int colBase = blockIdx.x * 128;

    // per-thread staging coordinates (2 chunks of 16B for each plane)
    const int ar0 = (tid * 2) >> 2,       ac0 = ((tid * 2) & 3) * 8;
    const int ar1 = (tid * 2 + 1) >> 2,   ac1 = ((tid * 2 + 1) & 3) * 8;
    const int br0 = (tid * 2) >> 4,       bc0 = ((tid * 2) & 15) * 8;
    const int br1 = (tid * 2 + 1) >> 4,   bc1 = ((tid * 2 + 1) & 15) * 8;

    auto prefetch = [&](int it, int s) {
        char* st = smem + s * STAGE_BYTES;
        const int kc = it * KC;
        __nv_bfloat16* sAh = (__nv_bfloat16*)(st + OFF_AH);
        __nv_bfloat16* sAl = (__nv_bfloat16*)(st + OFF_AL);
        __nv_bfloat16* sBh = (__nv_bfloat16*)(st + OFF_BH);
        __nv_bfloat16* sBl = (__nv_bfloat16*)(st + OFF_BL);
        size_t ga0 = (size_t)(rowBase + ar0) * DDIM + kc + ac0;
        size_t ga1 = (size_t)(rowBase + ar1) * DDIM + kc + ac1;
        cp16(&sAh[ar0 * LDA_S + ac0], Ah + ga0);
        cp16(&sAh[ar1 * LDA_S + ac1], Ah + ga1);
        cp16(&sAl[ar0 * LDA_S + ac0], Al + ga0);
        cp16(&sAl[ar1 * LDA_S + ac1], Al + ga1);
        size_t gb0 = (size_t)(kc + br0) * LDBG + colBase + bc0;
        size_t gb1 = (size_t)(kc + br1) * LDBG + colBase + bc1;
        cp16(&sBh[br0 * LDB_S + bc0], Bh + gb0);
        cp16(&sBh[br1 * LDB_S + bc1], Bh + gb1);
        cp16(&sBl[br0 * LDB_S + bc0], Bl + gb0);
        cp16(&sBl[br1 * LDB_S + bc1], Bl + gb1);
    };

    wmma::fragment<wmma::accumulator, 16, 16, 16, float> acc[4][2];
#pragma unroll
    for (int mi = 0; mi < 4; mi++)
#pragma unroll
        for (int ni = 0; ni < 2; ni++)
            wmma::load_matrix_sync(acc[mi][ni],
                                   btile + (colBase + wCol + ni * 16),
                                   LDC, wmma::mem_row_major);

    const int NIT = DDIM / KC;   // 16
    prefetch(0, 0);
    CP_COMMIT();

    for (int it = 0; it < NIT; it++) {
        const int cur = it & 1;
        if (it + 1 < NIT) {
            prefetch(it + 1, cur ^ 1);
            CP_COMMIT();
            cp_wait<1>();
        } else {
            cp_wait<0>();
        }
        __syncthreads();

        char* st = smem + cur * STAGE_BYTES;
        __nv_bfloat16* sAh = (__nv_bfloat16*)(st + OFF_AH);
        __nv_bfloat16* sAl = (__nv_bfloat16*)(st + OFF_AL);
        __nv_bfloat16* sBh = (__nv_bfloat16*)(st + OFF_BH);
        __nv_bfloat16* sBl = (__nv_bfloat16*)(st + OFF_BL);

#pragma unroll
        for (int k16 = 0; k16 < KC; k16 += 16) {
            wmma::fragment<wmma::matrix_a, 16, 16, 16, __nv_bfloat16, wmma::row_major> ah[4], al[4];
            wmma::fragment<wmma::matrix_b, 16, 16, 16, __nv_bfloat16, wmma::row_major> bh[2], bl[2];
#pragma unroll
            for (int mi = 0; mi < 4; mi++) {
                wmma::load_matrix_sync(ah[mi], &sAh[(wRow + mi * 16) * LDA_S + k16], LDA_S);
                wmma::load_matrix_sync(al[mi], &sAl[(wRow + mi * 16) * LDA_S + k16], LDA_S);
            }
#pragma unroll
            for (int ni = 0; ni < 2; ni++) {
                wmma::load_matrix_sync(bh[ni], &sBh[k16 * LDB_S + wCol + ni * 16], LDB_S);
                wmma::load_matrix_sync(bl[ni], &sBl[k16 * LDB_S + wCol + ni * 16], LDB_S);
            }
#pragma unroll
            for (int mi = 0; mi < 4; mi++)
#pragma unroll
                for (int ni = 0; ni < 2; ni++) {
                    wmma::mma_sync(acc[mi][ni], ah[mi], bh[ni], acc[mi][ni]);
                    wmma::mma_sync(acc[mi][ni], ah[mi], bl[ni], acc[mi][ni]);
                    wmma::mma_sync(acc[mi][ni], al[mi], bh[ni], acc[mi][ni]);
                }
        }
        __syncthreads();
    }

#pragma unroll
    for (int mi = 0; mi < 4; mi++)
#pragma unroll
        for (int ni = 0; ni < 2; ni++)
            wmma::store_matrix_sync(
                &C[(size_t)(rowBase + wRow + mi * 16) * LDC + colBase + wCol + ni * 16],
                acc[mi][ni], LDC, wmma::mem_row_major);
}

// ---------------------------------------------------------------------------
// Phase 1: scores. S[g][i][j] = Q_g[i] . K_g[j]  (unscaled), 128x128 tiles.
// grid (NG, 4, 4), block 256. Gathered rows, on-the-fly bf16 split, 3-combo.
// ---------------------------------------------------------------------------
#define SLDA 72     // 64 + 8 pad

__global__ __launch_bounds__(256)
void scores_kernel() {
    const int g = blockIdx.x, qt = blockIdx.y, kt = blockIdx.z;
    const int m = g_cnt[g];
    if (qt * 128 >= m || kt * 128 >= m) return;
    const int* mem = &g_mem[g * MAXG];

    extern __shared__ __nv_bfloat16 sm[];
    __nv_bfloat16* sQh = sm;
    __nv_bfloat16* sQl = sm + 128 * SLDA;
    __nv_bfloat16* sKh = sm + 2 * 128 * SLDA;
    __nv_bfloat16* sKl = sm + 3 * 128 * SLDA;

    const int tid = threadIdx.x;
    const int wid = tid >> 5;
    const int wRow = (wid & 1) * 64;
    const int wCol = (wid >> 1) * 32;

    wmma::fragment<wmma::accumulator, 16, 16, 16, float> acc[4][2];
#pragma unroll
    for (int mi = 0; mi < 4; mi++)
#pragma unroll
        for (int ni = 0; ni < 2; ni++)
            wmma::fill_fragment(acc[mi][ni], 0.f);

    for (int kc = 0; kc < DDIM; kc += 64) {
        for (int t = tid; t < 2048; t += 256) {
            int r = t >> 4, c4 = (t & 15) << 2;
            int qi = qt * 128 + r;
            float4 f = make_float4(0.f, 0.f, 0.f, 0.f);
            if (qi < m)
                f = *(const float4*)&g_qkv[(size_t)mem[qi] * NQKV + kc + c4];
            __nv_bfloat16 h0, h1, h2, h3, l0, l1, l2, l3;
            bsplit(f.x, h0, l0); bsplit(f.y, h1, l1);
            bsplit(f.z, h2, l2); bsplit(f.w, h3, l3);
            __nv_bfloat162* ph = (__nv_bfloat162*)&sQh[r * SLDA + c4];
            __nv_bfloat162* pl = (__nv_bfloat162*)&sQl[r * SLDA + c4];
            ph[0] = __nv_bfloat162(h0, h1); ph[1] = __nv_bfloat162(h2, h3);
            pl[0] = __nv_bfloat162(l0, l1); pl[1] = __nv_bfloat162(l2, l3);
        }
        for (int t = tid; t < 2048; t += 256) {
            int r = t >> 4, c4 = (t & 15) << 2;
            int ki = kt * 128 + r;
            float4 f = make_float4(0.f, 0.f, 0.f, 0.f);
            if (ki < m)
                f = *(const float4*)&g_qkv[(size_t)mem[ki] * NQKV + 512 + kc + c4];
            __nv_bfloat16 h0, h1, h2, h3, l0, l1, l2, l3;
            bsplit(f.x, h0, l0); bsplit(f.y, h1, l1);
            bsplit(f.z, h2, l2); bsplit(f.w, h3, l3);
            __nv_bfloat162* ph = (__nv_bfloat162*)&sKh[r * SLDA + c4];
            __nv_bfloat162* pl = (__nv_bfloat162*)&sKl[r * SLDA + c4];
            ph[0] = __nv_bfloat162(h0, h1); ph[1] = __nv_bfloat162(h2, h3);
            pl[0] = __nv_bfloat162(l0, l1); pl[1] = __nv_bfloat162(l2, l3);
        }
        __syncthreads();

#pragma unroll
        for (int k16 = 0; k16 < 64; k16 += 16) {
            wmma::fragment<wmma::matrix_a, 16, 16, 16, __nv_bfloat16, wmma::row_major> ah[4], al[4];
            wmma::fragment<wmma::matrix_b, 16, 16, 16, __nv_bfloat16, wmma::col_major> bh[2], bl[2];
#pragma unroll
            for (int mi = 0; mi < 4; mi++) {
                wmma::load_matrix_sync(ah[mi], &sQh[(wRow + mi * 16) * SLDA + k16], SLDA);
                wmma::load_matrix_sync(al[mi], &sQl[(wRow + mi * 16) * SLDA + k16], SLDA);
            }
#pragma unroll
            for (int ni = 0; ni < 2; ni++) {
                wmma::load_matrix_sync(bh[ni], &sKh[(wCol + ni * 16) * SLDA + k16], SLDA);
                wmma::load_matrix_sync(bl[ni], &sKl[(wCol + ni * 16) * SLDA + k16], SLDA);
            }
#pragma unroll
            for (int mi = 0; mi < 4; mi++)
#pragma unroll
                for (int ni = 0; ni < 2; ni++) {
                    wmma::mma_sync(acc[mi][ni], ah[mi], bh[ni], acc[mi][ni]);
                    wmma::mma_sync(acc[mi][ni], ah[mi], bl[ni], acc[mi][ni]);
                    wmma::mma_sync(acc[mi][ni], al[mi], bh[ni], acc[mi][ni]);
                }
        }
        __syncthreads();
    }

#pragma unroll
    for (int mi = 0; mi < 4; mi++)
#pragma unroll
        for (int ni = 0; ni < 2; ni++)
            wmma::store_matrix_sync(
                &g_S[((size_t)g * MAXG + qt * 128 + wRow + mi * 16) * MAXG
                     + kt * 128 + wCol + ni * 16],
                acc[mi][ni], MAXG, wmma::mem_row_major);
}

// ---------------------------------------------------------------------------
// Phase 2: softmax per row; writes P back in place as packed bf16 (hi|lo<<16)
// grid (NG, 64), block 256 (warp per row)
// ---------------------------------------------------------------------------
__global__ __launch_bounds__(256)
void softmax_kernel() {
    const int g = blockIdx.x;
    const int m = g_cnt[g];
    const int wid = threadIdx.x >> 5, lane = threadIdx.x & 31;
    const int i = blockIdx.y * 8 + wid;
    if (i >= m) return;
    float* rowp = &g_S[((size_t)g * MAXG + i) * MAXG];
    const float scale = 0.044194173824159216f;   // 1/sqrt(512)

    float vals[16];
    const int nt = (m + 31) >> 5;
    float mx = -1e30f;
    for (int t = 0; t < nt; t++) {
        int j = lane + t * 32;
        float v = (j < m) ? rowp[j] * scale : -1e30f;
        vals[t] = v;
        mx = fmaxf(mx, v);
    }
#pragma unroll
    for (int o = 16; o; o >>= 1) mx = fmaxf(mx, __shfl_xor_sync(0xffffffffu, mx, o));
    float sum = 0.f;
    for (int t = 0; t < nt; t++) {
        int j = lane + t * 32;
        float e = (j < m) ? __expf(vals[t] - mx) : 0.f;
        vals[t] = e;
        sum += e;
    }
#pragma unroll
    for (int o = 16; o; o >>= 1) sum += __shfl_xor_sync(0xffffffffu, sum, o);
    float inv = 1.f / sum;
    for (int t = 0; t < nt; t++) {
        int j = lane + t * 32;
        if (j < m) {
            float p = vals[t] * inv;
            __nv_bfloat16 h, l;
            bsplit(p, h, l);
            unsigned u = (unsigned)__bfloat16_as_ushort(h)
                       | ((unsigned)__bfloat16_as_ushort(l) << 16);
            ((unsigned*)rowp)[j] = u;
        }
    }
}

// ---------------------------------------------------------------------------
// Phase 3: out = P @ V_g, scattered + bf16-split directly into g_xh/g_xl.
// grid (NG, 4, 4=ntiles), block 256.
// ---------------------------------------------------------------------------
#define PLD 72
#define VLD 136

__global__ __launch_bounds__(256)
void pv_kernel() {
    const int g = blockIdx.x, qt = blockIdx.y, nt = blockIdx.z;
    const int m = g_cnt[g];
    if (qt * 128 >= m) return;
    const int* mem = &g_mem[g * MAXG];
    const int nbase = nt * 128;

    extern __shared__ __nv_bfloat16 sm2[];
    __nv_bfloat16* sPh = sm2;
    __nv_bfloat16* sPl = sm2 + 128 * PLD;
    __nv_bfloat16* sVh = sm2 + 2 * 128 * PLD;
    __nv_bfloat16* sVl = sVh + 64 * VLD;

    const int tid = threadIdx.x;
    const int wid = tid >> 5;
    const int wRow = (wid & 1) * 64;
    const int wCol = (wid >> 1) * 32;

    wmma::fragment<wmma::accumulator, 16, 16, 16, float> acc[4][2];
#pragma unroll
    for (int mi = 0; mi < 4; mi++)
#pragma unroll
        for (int ni = 0; ni < 2; ni++)
            wmma::fill_fragment(acc[mi][ni], 0.f);

    const int JT = (m + 63) >> 6;
    for (int jc = 0; jc < JT; jc++) {
        const int j0 = jc * 64;
        for (int t = tid; t < 8192; t += 256) {
            int r = t >> 6, c = t & 63;
            int j = j0 + c;
            unsigned u = 0;
            if (j < m)
                u = *(const unsigned*)&g_S[((size_t)g * MAXG + qt * 128 + r) * MAXG + j];
            sPh[r * PLD + c] = __ushort_as_bfloat16((unsigned short)(u & 0xffffu));
            sPl[r * PLD + c] = __ushort_as_bfloat16((unsigned short)(u >> 16));
        }
        for (int t = tid; t < 2048; t += 256) {
            int r = t >> 5, c4 = (t & 31) << 2;
            int j = j0 + r;
            float4 f = make_float4(0.f, 0.f, 0.f, 0.f);
            if (j < m)
                f = *(const float4*)&g_qkv[(size_t)mem[j] * NQKV + 1024 + nbase + c4];
            __nv_bfloat16 h0, h1, h2, h3, l0, l1, l2, l3;
            bsplit(f.x, h0, l0); bsplit(f.y, h1, l1);
            bsplit(f.z, h2, l2); bsplit(f.w, h3, l3);
            __nv_bfloat162* ph = (__nv_bfloat162*)&sVh[r * VLD + c4];
            __nv_bfloat162* pl = (__nv_bfloat162*)&sVl[r * VLD + c4];
            ph[0] = __nv_bfloat162(h0, h1); ph[1] = __nv_bfloat162(h2, h3);
            pl[0] = __nv_bfloat162(l0, l1); pl[1] = __nv_bfloat162(l2, l3);
        }
        __syncthreads();

#pragma unroll
        for (int k16 = 0; k16 < 64; k16 += 16) {
            wmma::fragment<wmma::matrix_a, 16, 16, 16, __nv_bfloat16, wmma::row_major> ah[4], al[4];
            wmma::fragment<wmma::matrix_b, 16, 16, 16, __nv_bfloat16, wmma::row_major> bh[2], bl[2];
#pragma unroll
            for (int mi = 0; mi < 4; mi++) {
                wmma::load_matrix_sync(ah[mi], &sPh[(wRow + mi * 16) * PLD + k16], PLD);
                wmma::load_matrix_sync(al[mi], &sPl[(wRow + mi * 16) * PLD + k16], PLD);
            }
#pragma unroll
            for (int ni = 0; ni < 2; ni++) {
                wmma::load_matrix_sync(bh[ni], &sVh[k16 * VLD + wCol + ni * 16], VLD);
                wmma::load_matrix_sync(bl[ni], &sVl[k16 * VLD + wCol + ni * 16], VLD);
            }
#pragma unroll
            for (int mi = 0; mi < 4; mi++)
#pragma unroll
                for (int ni = 0; ni < 2; ni++) {
                    wmma::mma_sync(acc[mi][ni], ah[mi], bh[ni], acc[mi][ni]);
                    wmma::mma_sync(acc[mi][ni], ah[mi], bl[ni], acc[mi][ni]);
                    wmma::mma_sync(acc[mi][ni], al[mi], bh[ni], acc[mi][ni]);
                }
        }
        __syncthreads();
    }

    // stage output tile in smem (reuse), then scatter + split to g_xh/g_xl
    float* so = (float*)sm2;   // 128 x 132
#pragma unroll
    for (int mi = 0; mi < 4; mi++)
#pragma unroll
        for (int ni = 0; ni < 2; ni++)
            wmma::store_matrix_sync(&so[(wRow + mi * 16) * 132 + wCol + ni * 16],
                                    acc[mi][ni], 132, wmma::mem_row_major);
    __syncthreads();

    for (int t = tid; t < 4096; t += 256) {
        int r = t >> 5, c4 = (t & 31) << 2;
        int i = qt * 128 + r;
        if (i < m) {
            int row = mem[i];
            float4 f = *(float4*)&so[r * 132 + c4];
            __nv_bfloat16 h0, h1, h2, h3, l0, l1, l2, l3;
            bsplit(f.x, h0, l0); bsplit(f.y, h1, l1);
            bsplit(f.z, h2, l2); bsplit(f.w, h3, l3);
            size_t o = ((size_t)row * DDIM + nbase + c4) >> 1;   // bf162 index
            ((__nv_bfloat162*)g_xh)[o]     = __nv_bfloat162(h0, h1);
            ((__nv_bfloat162*)g_xh)[o + 1] = __nv_bfloat162(h2, h3);
            ((__nv_bfloat162*)g_xl)[o]     = __nv_bfloat162(l0, l1);
            ((__nv_bfloat162*)g_xl)[o + 1] = __nv_bfloat162(l2, l3);
        }
    }
}

// ---------------------------------------------------------------------------
// Launch
// ---------------------------------------------------------------------------
extern "C" void kernel_launch(void* const* d_in, const int* in_sizes, int n_in,
                              void* d_out, int out_size) {
    const float* x      = (const float*)d_in[0];
    const int*   labels = (const int*)  d_in[1];
    const float* Wq     = (const float*)d_in[2];
    const float* bq     = (const float*)d_in[3];
    const float* Wk     = (const float*)d_in[4];
    const float* bk     = (const float*)d_in[5];
    const float* Wv     = (const float*)d_in[6];
    const float* bv     = (const float*)d_in[7];
    const float* Wo     = (const float*)d_in[8];
    const float* bo     = (const float*)d_in[9];
    float* out = (float*)d_out;

    float *qkv, *btq, *bto;
    __nv_bfloat16 *xh, *xl, *pwh, *pwl, *owh, *owl;
    cudaGetSymbolAddress((void**)&qkv, g_qkv);
    cudaGetSymbolAddress((void**)&btq, g_btq);
    cudaGetSymbolAddress((void**)&bto, g_bto);
    cudaGetSymbolAddress((void**)&xh,  g_xh);
    cudaGetSymbolAddress((void**)&xl,  g_xl);
    cudaGetSymbolAddress((void**)&pwh, g_pwh);
    cudaGetSymbolAddress((void**)&pwl, g_pwl);
    cudaGetSymbolAddress((void**)&owh, g_owh);
    cudaGetSymbolAddress((void**)&owl, g_owl);

    const int scores_smem = 4 * 128 * SLDA * (int)sizeof(__nv_bfloat16);    // 73728
    const int pv_smem = (2 * 128 * PLD + 2 * 64 * VLD) * (int)sizeof(__nv_bfloat16); // 71680
    cudaFuncSetAttribute(scores_kernel, cudaFuncAttributeMaxDynamicSharedMemorySize, scores_smem);
    cudaFuncSetAttribute(pv_kernel, cudaFuncAttributeMaxDynamicSharedMemorySize, pv_smem);
    cudaFuncSetAttribute(wmma_gemm_kernel<NQKV, NQKV>,
                         cudaFuncAttributeMaxDynamicSharedMemorySize, GEMM_SMEM);
    cudaFuncSetAttribute(wmma_gemm_kernel<DDIM, DDIM>,
                         cudaFuncAttributeMaxDynamicSharedMemorySize, GEMM_SMEM);

    zero_cnt_kernel<<<1, 64>>>();
    build_groups_kernel<<<NROWS / 256, 256>>>(labels);
    split_kernel<<<(NROWS * DDIM / 4) / 256, 256>>>(x, xh, xl);
    pack_weights_kernel<<<(4 * DDIM * DDIM) / 256, 256>>>(Wq, Wk, Wv, Wo);
    bias_tile_kernel<<<(16 * 2048) / 256, 256>>>(bq, bk, bv, bo);

    // fused QKV projection: [8192,512] @ [512,1536] + bias
    wmma_gemm_kernel<NQKV, NQKV><<<dim3(NQKV / 128, NROWS / 128), 256, GEMM_SMEM>>>(
        xh, xl, pwh, pwl, btq, qkv);

    scores_kernel<<<dim3(NG, 4, 4), 256, scores_smem>>>();
    softmax_kernel<<<dim3(NG, 64), 256>>>();
    zero_invalid_kernel<<<(NROWS * 64) / 256, 256>>>(labels);
    pv_kernel<<<dim3(NG, 4, 4), 256, pv_smem>>>();

    // output projection straight into d_out
    wmma_gemm_kernel<DDIM, DDIM><<<dim3(DDIM / 128, NROWS / 128), 256, GEMM_SMEM>>>(
        xh, xl, owh, owl, bto, out);
}